// round 1
// baseline (speedup 1.0000x reference)
#include <cuda_runtime.h>

#define NB 32
#define NN 100000
#define NE 1000000
#define NH 64
#define NL 3
#define NRELP 231
#define NENT 7128
#define NTIME 365
#define FULLM 0xffffffffu

// ---------------- device scratch (no allocation allowed) ----------------
static __device__ float g_hidden[NN * NH];   // 25.6 MB
static __device__ float g_next[NN * NH];     // 25.6 MB
static __device__ int   g_perm[NE];          // 4 MB
static __device__ int   g_cnt[3];
static __device__ int   g_cur[3];

__device__ __forceinline__ int edge_class(int rt) {
    return rt > 0 ? 2 : (rt == 0 ? 1 : 0);   // 0=past(Wp) 1=now(Wn) 2=future(Wf)
}

// ---------------- init ----------------
__global__ void zero_state_kernel() {
    int i = blockIdx.x * blockDim.x + threadIdx.x;
    const int n4 = NN * NH / 4;
    if (i < n4) {
        ((float4*)g_hidden)[i] = make_float4(0.f, 0.f, 0.f, 0.f);
        ((float4*)g_next)[i]   = make_float4(0.f, 0.f, 0.f, 0.f);
    }
}

__global__ void zero_out_kernel(float* out, int n) {
    int i = blockIdx.x * blockDim.x + threadIdx.x;
    if (i < n) out[i] = 0.f;
}

// ---------------- partition edges by time-sign class ----------------
__global__ void part_reset_kernel() {
    if (threadIdx.x < 3) g_cnt[threadIdx.x] = 0;
}

__global__ void count_kernel(const int* __restrict__ rel_time) {
    __shared__ int sc[3];
    if (threadIdx.x < 3) sc[threadIdx.x] = 0;
    __syncthreads();
    int lane = threadIdx.x & 31;
    int stride = gridDim.x * blockDim.x;
    for (int base = blockIdx.x * blockDim.x; base < NE; base += stride) {
        int e = base + threadIdx.x;
        int c = (e < NE) ? edge_class(rel_time[e]) : -1;
#pragma unroll
        for (int cls = 0; cls < 3; ++cls) {
            unsigned m = __ballot_sync(FULLM, c == cls);
            if (m && lane == (__ffs(m) - 1)) atomicAdd(&sc[cls], __popc(m));
        }
    }
    __syncthreads();
    if (threadIdx.x < 3) atomicAdd(&g_cnt[threadIdx.x], sc[threadIdx.x]);
}

__global__ void offsets_kernel() {
    g_cur[0] = 0;
    g_cur[1] = g_cnt[0];
    g_cur[2] = g_cnt[0] + g_cnt[1];
}

__global__ void scatter_kernel(const int* __restrict__ rel_time) {
    int lane = threadIdx.x & 31;
    int stride = gridDim.x * blockDim.x;
    for (int base = blockIdx.x * blockDim.x; base < NE; base += stride) {
        int e = base + threadIdx.x;
        int c = (e < NE) ? edge_class(rel_time[e]) : -1;
#pragma unroll
        for (int cls = 0; cls < 3; ++cls) {
            unsigned m = __ballot_sync(FULLM, c == cls);
            if (!m) continue;
            int leader = __ffs(m) - 1;
            int b = 0;
            if (lane == leader) b = atomicAdd(&g_cur[cls], __popc(m));
            b = __shfl_sync(FULLM, b, leader);
            if (c == cls) g_perm[b + __popc(m & ((1u << lane) - 1u))] = e;
        }
    }
}

// ---------------- main edge kernel ----------------
// Warp processes 4 edges at a time. Lane l owns output dims (2l, 2l+1).
// sWT holds transposed W (column-major by k) with XOR swizzle for conflict-free
// LDS.64 in the hot loop AND low-conflict one-time transpose store.
__global__ void __launch_bounds__(256, 3) edge_kernel(
    const float* __restrict__ rela, const float* __restrict__ temb,
    const float* __restrict__ Wp, const float* __restrict__ Wn,
    const float* __restrict__ Wf,
    const float* __restrict__ W1, const float* __restrict__ W2,
    const int* __restrict__ src_idx, const int* __restrict__ dst_idx,
    const int* __restrict__ rel_idx, const int* __restrict__ rel_time,
    const int* __restrict__ batch_idx, const int* __restrict__ query_rel,
    int layer)
{
    __shared__ float sWT[3 * 64 * 64];   // 48 KB: [class][k][h] swizzled

    int tid = threadIdx.x, lane = tid & 31;

    // fill smem: element W_c[h][k] -> class c, row k, float2 cell (h>>1)^(k&31), comp h&1
    for (int g = tid; g < 3 * 4096; g += blockDim.x) {
        int c = g >> 12;
        int r = g & 4095;
        int h = r >> 6;
        int k = r & 63;
        const float* W = (c == 0) ? Wp : ((c == 1) ? Wn : Wf);
        int cell = (k << 5) + (((h >> 1) ^ k) & 31);
        sWT[(c << 12) + 2 * cell + (h & 1)] = __ldg(&W[(h << 6) + k]);
    }

    const float* lb = rela + layer * NRELP * NH;

    // attention weights: per-lane registers (lane l always uses dims 2l,2l+1)
    float2 w1r[5][3];
#pragma unroll
    for (int a = 0; a < 5; ++a)
#pragma unroll
        for (int s3 = 0; s3 < 3; ++s3)
            w1r[a][s3] = *(const float2*)&W1[(layer * 5 + a) * 192 + s3 * 64 + 2 * lane];
    float w2r[5];
#pragma unroll
    for (int a = 0; a < 5; ++a) w2r[a] = __ldg(&W2[layer * 5 + a]);

    __syncthreads();

    int gw = (blockIdx.x * blockDim.x + tid) >> 5;
    int nw = (gridDim.x * blockDim.x) >> 5;

    for (int base = gw * 4; base < NE; base += nw * 4) {
        int dstI[4], cI[4];
        float sI[4];
        float2 emI[4];

#pragma unroll
        for (int t = 0; t < 4; ++t) {
            int e   = __ldg(&g_perm[base + t]);
            int src = __ldg(&src_idx[e]);
            dstI[t] = __ldg(&dst_idx[e]);
            int rel = __ldg(&rel_idx[e]);
            int rt  = __ldg(&rel_time[e]);
            int bi  = __ldg(&batch_idx[e]);
            int qr  = __ldg(&query_rel[bi]);
            cI[t] = edge_class(rt);
            int ta = rt < 0 ? -rt : rt;

            float2 hs = *(const float2*)&g_hidden[src * 64 + 2 * lane];
            float2 re = *(const float2*)&lb[rel * 64 + 2 * lane];
            float2 te = *(const float2*)&temb[ta * 64 + 2 * lane];
            float2 qe = *(const float2*)&lb[qr * 64 + 2 * lane];

            emI[t].x = hs.x + re.x + te.x;
            emI[t].y = hs.y + re.y + te.y;

            float p[5];
#pragma unroll
            for (int a = 0; a < 5; ++a)
                p[a] = hs.x * w1r[a][0].x + hs.y * w1r[a][0].y
                     + re.x * w1r[a][1].x + re.y * w1r[a][1].y
                     + qe.x * w1r[a][2].x + qe.y * w1r[a][2].y;
#pragma unroll
            for (int a = 0; a < 5; ++a)
#pragma unroll
                for (int off = 16; off; off >>= 1)
                    p[a] += __shfl_xor_sync(FULLM, p[a], off);
            float zs = 0.f;
#pragma unroll
            for (int a = 0; a < 5; ++a) zs += fmaxf(p[a], 0.f) * w2r[a];
            sI[t] = 1.f / (1.f + __expf(-zs));
        }

        float2 A0 = make_float2(0.f, 0.f), A1 = A0, A2 = A0, A3 = A0;

        if (cI[0] == cI[1] && cI[0] == cI[2] && cI[0] == cI[3]) {
            const float2* w0 = (const float2*)(sWT + (cI[0] << 12));
#pragma unroll 8
            for (int k2 = 0; k2 < 32; ++k2) {
                float2 wA = w0[(2 * k2) * 32 + (lane ^ ((2 * k2) & 31))];
                float2 wB = w0[(2 * k2 + 1) * 32 + (lane ^ ((2 * k2 + 1) & 31))];
                float b, d;
                b = __shfl_sync(FULLM, emI[0].x, k2); A0.x += b * wA.x; A0.y += b * wA.y;
                d = __shfl_sync(FULLM, emI[0].y, k2); A0.x += d * wB.x; A0.y += d * wB.y;
                b = __shfl_sync(FULLM, emI[1].x, k2); A1.x += b * wA.x; A1.y += b * wA.y;
                d = __shfl_sync(FULLM, emI[1].y, k2); A1.x += d * wB.x; A1.y += d * wB.y;
                b = __shfl_sync(FULLM, emI[2].x, k2); A2.x += b * wA.x; A2.y += b * wA.y;
                d = __shfl_sync(FULLM, emI[2].y, k2); A2.x += d * wB.x; A2.y += d * wB.y;
                b = __shfl_sync(FULLM, emI[3].x, k2); A3.x += b * wA.x; A3.y += b * wA.y;
                d = __shfl_sync(FULLM, emI[3].y, k2); A3.x += d * wB.x; A3.y += d * wB.y;
            }
        } else {
            // rare: class boundary inside group — per-edge W base
            float2* Ap[4] = {&A0, &A1, &A2, &A3};
#pragma unroll
            for (int t = 0; t < 4; ++t) {
                const float2* w0 = (const float2*)(sWT + (cI[t] << 12));
                float2 acc = make_float2(0.f, 0.f);
#pragma unroll 8
                for (int k2 = 0; k2 < 32; ++k2) {
                    float2 wA = w0[(2 * k2) * 32 + (lane ^ ((2 * k2) & 31))];
                    float2 wB = w0[(2 * k2 + 1) * 32 + (lane ^ ((2 * k2 + 1) & 31))];
                    float b = __shfl_sync(FULLM, emI[t].x, k2);
                    acc.x += b * wA.x; acc.y += b * wA.y;
                    float d = __shfl_sync(FULLM, emI[t].y, k2);
                    acc.x += d * wB.x; acc.y += d * wB.y;
                }
                *Ap[t] = acc;
            }
        }

        {
            float vx, vy;
            float* p;
            vx = sI[0] * A0.x; vy = sI[0] * A0.y;
            p = &g_next[dstI[0] * 64 + 2 * lane];
            asm volatile("red.global.add.v2.f32 [%0], {%1, %2};" :: "l"(p), "f"(vx), "f"(vy) : "memory");
            vx = sI[1] * A1.x; vy = sI[1] * A1.y;
            p = &g_next[dstI[1] * 64 + 2 * lane];
            asm volatile("red.global.add.v2.f32 [%0], {%1, %2};" :: "l"(p), "f"(vx), "f"(vy) : "memory");
            vx = sI[2] * A2.x; vy = sI[2] * A2.y;
            p = &g_next[dstI[2] * 64 + 2 * lane];
            asm volatile("red.global.add.v2.f32 [%0], {%1, %2};" :: "l"(p), "f"(vx), "f"(vy) : "memory");
            vx = sI[3] * A3.x; vy = sI[3] * A3.y;
            p = &g_next[dstI[3] * 64 + 2 * lane];
            asm volatile("red.global.add.v2.f32 [%0], {%1, %2};" :: "l"(p), "f"(vx), "f"(vy) : "memory");
        }
    }
}

// ---------------- hidden = relu(next); next = 0 ----------------
__global__ void relu_reset_kernel() {
    int i = blockIdx.x * blockDim.x + threadIdx.x;
    const int n4 = NN * NH / 4;
    if (i < n4) {
        float4 v = ((float4*)g_next)[i];
        v.x = fmaxf(v.x, 0.f); v.y = fmaxf(v.y, 0.f);
        v.z = fmaxf(v.z, 0.f); v.w = fmaxf(v.w, 0.f);
        ((float4*)g_hidden)[i] = v;
        ((float4*)g_next)[i] = make_float4(0.f, 0.f, 0.f, 0.f);
    }
}

// ---------------- output: dot(hidden, Wc)+bc scattered into [B, N_ENT] ----------------
__global__ void out_kernel(const float* __restrict__ Wc, const float* __restrict__ bc,
                           const int* __restrict__ ob, const int* __restrict__ oe,
                           float* __restrict__ out) {
    int gw = (blockIdx.x * blockDim.x + threadIdx.x) >> 5;
    int lane = threadIdx.x & 31;
    if (gw >= NN) return;
    float2 h = *(const float2*)&g_hidden[gw * 64 + 2 * lane];
    float2 w = *(const float2*)&Wc[2 * lane];
    float p = h.x * w.x + h.y * w.y;
#pragma unroll
    for (int off = 16; off; off >>= 1) p += __shfl_xor_sync(FULLM, p, off);
    if (lane == 0) out[ob[gw] * NENT + oe[gw]] = p + bc[0];
}

// ---------------- host launch ----------------
extern "C" void kernel_launch(void* const* d_in, const int* in_sizes, int n_in,
                              void* d_out, int out_size) {
    const int *bt, *si, *di, *ri, *rt, *qr, *ob, *oe;
    const float *rela, *te, *Wp, *Wn, *Wf, *W1, *W2, *Wc, *bc;

    if (in_sizes[0] == NE) {
        // setup_inputs dict order
        bt = (const int*)d_in[0];  si = (const int*)d_in[1];
        di = (const int*)d_in[2];  ri = (const int*)d_in[3];
        rt = (const int*)d_in[4];  qr = (const int*)d_in[5];
        ob = (const int*)d_in[6];  oe = (const int*)d_in[7];
        rela = (const float*)d_in[8];  te = (const float*)d_in[9];
        Wp = (const float*)d_in[10]; Wn = (const float*)d_in[11];
        Wf = (const float*)d_in[12]; W1 = (const float*)d_in[13];
        W2 = (const float*)d_in[14]; Wc = (const float*)d_in[15];
        bc = (const float*)d_in[16];
    } else {
        // reference signature order
        rela = (const float*)d_in[0];  te = (const float*)d_in[1];
        Wp = (const float*)d_in[2]; Wn = (const float*)d_in[3];
        Wf = (const float*)d_in[4]; W1 = (const float*)d_in[5];
        W2 = (const float*)d_in[6]; Wc = (const float*)d_in[7];
        bc = (const float*)d_in[8];
        bt = (const int*)d_in[9];  si = (const int*)d_in[10];
        di = (const int*)d_in[11]; ri = (const int*)d_in[12];
        rt = (const int*)d_in[13]; qr = (const int*)d_in[14];
        ob = (const int*)d_in[15]; oe = (const int*)d_in[16];
    }

    float* out = (float*)d_out;

    const int n4 = NN * NH / 4;
    zero_state_kernel<<<(n4 + 255) / 256, 256>>>();
    zero_out_kernel<<<(out_size + 255) / 256, 256>>>(out, out_size);

    part_reset_kernel<<<1, 32>>>();
    count_kernel<<<512, 256>>>(rt);
    offsets_kernel<<<1, 1>>>();
    scatter_kernel<<<512, 256>>>(rt);

    for (int layer = 0; layer < NL; ++layer) {
        edge_kernel<<<456, 256>>>(rela, te, Wp, Wn, Wf, W1, W2,
                                  si, di, ri, rt, bt, qr, layer);
        relu_reset_kernel<<<(n4 + 255) / 256, 256>>>();
    }

    out_kernel<<<(NN * 32 + 255) / 256, 256>>>(Wc, bc, ob, oe, out);
}

// round 2
// speedup vs baseline: 1.8145x; 1.8145x over previous
#include <cuda_runtime.h>

#define NB 32
#define NN 100000
#define NE 1000000
#define NH 64
#define NL 3
#define NRELP 231
#define NENT 7128
#define FULLM 0xffffffffu

typedef unsigned long long ull;

// ---------------- device scratch ----------------
static __device__ float g_hidden[NN * NH];     // 25.6 MB
static __device__ float g_next[NN * NH];       // 25.6 MB
static __device__ int   g_srcS[NE];
static __device__ int   g_dstS[NE];
static __device__ int   g_metaS[NE];           // ta | rel<<16 | cls<<28
static __device__ int   g_sciS[NE];            // bi*NRELP + rel
static __device__ float g_hv[NN * 8];          // per-node attention partials
static __device__ float g_rq[NB * NRELP * 8];  // per-(batch,rel) attention partials
static __device__ int   g_cnt[3], g_cur[3];

#define FMA2(d, a, b, c) \
    asm("fma.rn.f32x2 %0, %1, %2, %3;" : "=l"(d) : "l"(a), "l"(b), "l"(c))

__device__ __forceinline__ ull dup_f(float x) {
    ull r; unsigned u = __float_as_uint(x);
    asm("mov.b64 %0, {%1, %1};" : "=l"(r) : "r"(u));
    return r;
}
__device__ __forceinline__ void red2(float* p, float x, float y) {
    asm volatile("red.global.add.v2.f32 [%0], {%1, %2};" :: "l"(p), "f"(x), "f"(y) : "memory");
}
__device__ __forceinline__ int edge_class(int rt) {
    return rt > 0 ? 2 : (rt == 0 ? 1 : 0);   // 0=past(Wp) 1=now(Wn) 2=future(Wf)
}

// ---------------- init ----------------
__global__ void zero_state_kernel() {
    int i = blockIdx.x * blockDim.x + threadIdx.x;
    const int n4 = NN * NH / 4;
    if (i < n4) {
        ((float4*)g_hidden)[i] = make_float4(0.f, 0.f, 0.f, 0.f);
        ((float4*)g_next)[i]   = make_float4(0.f, 0.f, 0.f, 0.f);
    }
}

__global__ void zero_out_kernel(float* out, int n) {
    int i = blockIdx.x * blockDim.x + threadIdx.x;
    if (i < n) out[i] = 0.f;
}

// ---------------- partition edges by time-sign class ----------------
__global__ void part_reset_kernel() {
    if (threadIdx.x < 3) g_cnt[threadIdx.x] = 0;
}

__global__ void count_kernel(const int* __restrict__ rel_time) {
    __shared__ int sc[3];
    if (threadIdx.x < 3) sc[threadIdx.x] = 0;
    __syncthreads();
    int lane = threadIdx.x & 31;
    int stride = gridDim.x * blockDim.x;
    for (int base = blockIdx.x * blockDim.x; base < NE; base += stride) {
        int e = base + threadIdx.x;
        int c = (e < NE) ? edge_class(rel_time[e]) : -1;
#pragma unroll
        for (int cls = 0; cls < 3; ++cls) {
            unsigned m = __ballot_sync(FULLM, c == cls);
            if (m && lane == (__ffs(m) - 1)) atomicAdd(&sc[cls], __popc(m));
        }
    }
    __syncthreads();
    if (threadIdx.x < 3) atomicAdd(&g_cnt[threadIdx.x], sc[threadIdx.x]);
}

__global__ void offsets_kernel() {
    g_cur[0] = 0;
    g_cur[1] = g_cnt[0];
    g_cur[2] = g_cnt[0] + g_cnt[1];
}

__global__ void scatter_kernel(const int* __restrict__ rel_time,
                               const int* __restrict__ src_idx,
                               const int* __restrict__ dst_idx,
                               const int* __restrict__ rel_idx,
                               const int* __restrict__ batch_idx) {
    int lane = threadIdx.x & 31;
    int stride = gridDim.x * blockDim.x;
    for (int base = blockIdx.x * blockDim.x; base < NE; base += stride) {
        int e = base + threadIdx.x;
        int c = (e < NE) ? edge_class(rel_time[e]) : -1;
#pragma unroll
        for (int cls = 0; cls < 3; ++cls) {
            unsigned m = __ballot_sync(FULLM, c == cls);
            if (!m) continue;
            int leader = __ffs(m) - 1;
            int b = 0;
            if (lane == leader) b = atomicAdd(&g_cur[cls], __popc(m));
            b = __shfl_sync(FULLM, b, leader);
            if (c == cls) {
                int pos = b + __popc(m & ((1u << lane) - 1u));
                int rt = rel_time[e];
                int ta = rt < 0 ? -rt : rt;
                int rel = rel_idx[e];
                g_srcS[pos]  = src_idx[e];
                g_dstS[pos]  = dst_idx[e];
                g_metaS[pos] = ta | (rel << 16) | (cls << 28);
                g_sciS[pos]  = batch_idx[e] * NRELP + rel;
            }
        }
    }
}

// ---------------- per-layer attention precompute ----------------
// hv[n][a] = hidden[n] . W1[l][a][0:64]
__global__ void hv_kernel(const float* __restrict__ W1L) {
    int w = (blockIdx.x * blockDim.x + threadIdx.x) >> 5;
    int lane = threadIdx.x & 31;
    if (w >= NN) return;
    float2 h = *(const float2*)&g_hidden[w * 64 + 2 * lane];
    float p[5];
#pragma unroll
    for (int a = 0; a < 5; ++a) {
        float2 u = *(const float2*)&W1L[a * 192 + 2 * lane];
        p[a] = h.x * u.x + h.y * u.y;
    }
#pragma unroll
    for (int a = 0; a < 5; ++a)
#pragma unroll
        for (int off = 16; off; off >>= 1) p[a] += __shfl_xor_sync(FULLM, p[a], off);
    if (lane == 0) {
#pragma unroll
        for (int a = 0; a < 5; ++a) g_hv[w * 8 + a] = p[a];
    }
}

// rq[b*231+r][a] = rela[r].W1seg1_a + rela[qr_b].W1seg2_a
__global__ void rq_kernel(const float* __restrict__ relaL,
                          const float* __restrict__ W1L,
                          const int* __restrict__ query_rel) {
    int w = (blockIdx.x * blockDim.x + threadIdx.x) >> 5;
    int lane = threadIdx.x & 31;
    if (w >= NB * NRELP) return;
    int b = w / NRELP, r = w % NRELP;
    int qrb = __ldg(&query_rel[b]);
    float2 re = *(const float2*)&relaL[r * 64 + 2 * lane];
    float2 qe = *(const float2*)&relaL[qrb * 64 + 2 * lane];
    float p[5];
#pragma unroll
    for (int a = 0; a < 5; ++a) {
        float2 v = *(const float2*)&W1L[a * 192 + 64 + 2 * lane];
        float2 ww = *(const float2*)&W1L[a * 192 + 128 + 2 * lane];
        p[a] = re.x * v.x + re.y * v.y + qe.x * ww.x + qe.y * ww.y;
    }
#pragma unroll
    for (int a = 0; a < 5; ++a)
#pragma unroll
        for (int off = 16; off; off >>= 1) p[a] += __shfl_xor_sync(FULLM, p[a], off);
    if (lane == 0) {
#pragma unroll
        for (int a = 0; a < 5; ++a) g_rq[w * 8 + a] = p[a];
    }
}

// ---------------- main edge kernel ----------------
// Tile of 128 edges per block iteration.
// A: 128 threads compute scores (precomputed partials, no shfl)
// B: coalesced gather of score*(hs+re+te) into smem tile (stride 66 = conflict-free)
// C: thread-per-(edge,half): 32 output dims in registers, FFMA2 matvec from smem W
__global__ void __launch_bounds__(256, 2) edge_kernel(
    const float* __restrict__ relaL, const float* __restrict__ timeE,
    const float* __restrict__ Wp, const float* __restrict__ Wn,
    const float* __restrict__ Wf, const float* __restrict__ W2L, int isL0)
{
    extern __shared__ float dyn[];
    float* sW   = dyn;              // 3*64*68 = 13056 floats (52224 B)
    float* sEmb = dyn + 3 * 4352;   // 128*66  =  8448 floats (33792 B)
    __shared__ float sScore[128];
    __shared__ int   sSrc[128], sRT[128], sDstC[128];

    int t = threadIdx.x;

    // W fill: sW[c][k][h'] with halves at float offsets 0 and 36 (bank-disjoint)
    for (int idx = t; idx < 3 * 4096; idx += 256) {
        int c = idx >> 12, rem = idx & 4095;
        int h = rem >> 6, k = rem & 63;
        const float* W = (c == 0) ? Wp : ((c == 1) ? Wn : Wf);
        sW[c * 4352 + k * 68 + h + (h >= 32 ? 4 : 0)] = __ldg(&W[h * 64 + k]);
    }
    float w2r[5];
#pragma unroll
    for (int a = 0; a < 5; ++a) w2r[a] = __ldg(&W2L[a]);
    __syncthreads();

    for (int tile = blockIdx.x * 128; tile < NE; tile += gridDim.x * 128) {
        int nE = min(128, NE - tile);

        // ---- A: scores + metadata ----
        if (t < nE) {
            int e = tile + t;
            int src = g_srcS[e];
            int m1  = g_metaS[e];
            int sci = g_sciS[e];
            int dst = g_dstS[e];
            const float4* rq4 = (const float4*)&g_rq[sci * 8];
            float4 r0 = rq4[0], r1 = rq4[1];
            float p0 = r0.x, p1 = r0.y, p2 = r0.z, p3 = r0.w, p4 = r1.x;
            if (!isL0) {
                const float4* hv4 = (const float4*)&g_hv[src * 8];
                float4 h0 = hv4[0], h1 = hv4[1];
                p0 += h0.x; p1 += h0.y; p2 += h0.z; p3 += h0.w; p4 += h1.x;
            }
            float z = fmaxf(p0, 0.f) * w2r[0] + fmaxf(p1, 0.f) * w2r[1]
                    + fmaxf(p2, 0.f) * w2r[2] + fmaxf(p3, 0.f) * w2r[3]
                    + fmaxf(p4, 0.f) * w2r[4];
            sScore[t] = 1.f / (1.f + __expf(-z));
            sSrc[t] = src;
            sRT[t]  = m1;
            sDstC[t] = dst | ((m1 >> 28) << 20);
        }
        __syncthreads();

        // ---- B: coalesced gather -> scaled embed tile ----
        for (int j = t; j < nE * 32; j += 256) {
            int el = j >> 5, l = j & 31;
            int m1 = sRT[el];
            int ta = m1 & 0xFFFF, rel = (m1 >> 16) & 0xFFF;
            float s = sScore[el];
            float2 v  = *(const float2*)&relaL[rel * 64 + 2 * l];
            float2 tv = *(const float2*)&timeE[ta * 64 + 2 * l];
            v.x += tv.x; v.y += tv.y;
            if (!isL0) {
                float2 h = *(const float2*)&g_hidden[sSrc[el] * 64 + 2 * l];
                v.x += h.x; v.y += h.y;
            }
            v.x *= s; v.y *= s;
            *(float2*)&sEmb[el * 66 + 2 * l] = v;
        }
        __syncthreads();

        // ---- C: thread-per-(edge,half) FFMA2 matvec + RED scatter ----
        int slot = t >> 1, p = t & 1;
        if (slot < nE) {
            int dc = sDstC[slot];
            int dst = dc & 0xFFFFF;
            int cls = dc >> 20;
            const float* wb = sW + cls * 4352 + p * 36;
            ull acc[16];
#pragma unroll
            for (int j = 0; j < 16; ++j) acc[j] = 0ull;
            const float* er = sEmb + slot * 66;
#pragma unroll 4
            for (int k2 = 0; k2 < 32; ++k2) {
                float2 e2 = *(const float2*)&er[2 * k2];
                ull b0 = dup_f(e2.x);
                ull b1 = dup_f(e2.y);
                const float* r0 = wb + (2 * k2) * 68;
                const float* r1 = r0 + 68;
#pragma unroll
                for (int j = 0; j < 8; ++j) {
                    ulonglong2 w0 = *(const ulonglong2*)(r0 + 4 * j);
                    FMA2(acc[2 * j],     w0.x, b0, acc[2 * j]);
                    FMA2(acc[2 * j + 1], w0.y, b0, acc[2 * j + 1]);
                }
#pragma unroll
                for (int j = 0; j < 8; ++j) {
                    ulonglong2 w1 = *(const ulonglong2*)(r1 + 4 * j);
                    FMA2(acc[2 * j],     w1.x, b1, acc[2 * j]);
                    FMA2(acc[2 * j + 1], w1.y, b1, acc[2 * j + 1]);
                }
            }
            float* ob = g_next + dst * 64 + p * 32;
#pragma unroll
            for (int j = 0; j < 16; ++j) {
                float2 a = *(float2*)&acc[j];
                red2(ob + 2 * j, a.x, a.y);
            }
        }
        __syncthreads();
    }
}

// ---------------- hidden = relu(next); next = 0 ----------------
__global__ void relu_reset_kernel() {
    int i = blockIdx.x * blockDim.x + threadIdx.x;
    const int n4 = NN * NH / 4;
    if (i < n4) {
        float4 v = ((float4*)g_next)[i];
        v.x = fmaxf(v.x, 0.f); v.y = fmaxf(v.y, 0.f);
        v.z = fmaxf(v.z, 0.f); v.w = fmaxf(v.w, 0.f);
        ((float4*)g_hidden)[i] = v;
        ((float4*)g_next)[i] = make_float4(0.f, 0.f, 0.f, 0.f);
    }
}

// ---------------- output ----------------
__global__ void out_kernel(const float* __restrict__ Wc, const float* __restrict__ bc,
                           const int* __restrict__ ob, const int* __restrict__ oe,
                           float* __restrict__ out) {
    int gw = (blockIdx.x * blockDim.x + threadIdx.x) >> 5;
    int lane = threadIdx.x & 31;
    if (gw >= NN) return;
    float2 h = *(const float2*)&g_hidden[gw * 64 + 2 * lane];
    float2 w = *(const float2*)&Wc[2 * lane];
    float p = h.x * w.x + h.y * w.y;
#pragma unroll
    for (int off = 16; off; off >>= 1) p += __shfl_xor_sync(FULLM, p, off);
    if (lane == 0) out[ob[gw] * NENT + oe[gw]] = p + bc[0];
}

// ---------------- host launch ----------------
extern "C" void kernel_launch(void* const* d_in, const int* in_sizes, int n_in,
                              void* d_out, int out_size) {
    const int *bt, *si, *di, *ri, *rt, *qr, *ob, *oe;
    const float *rela, *te, *Wp, *Wn, *Wf, *W1, *W2, *Wc, *bc;

    if (in_sizes[0] == NE) {
        bt = (const int*)d_in[0];  si = (const int*)d_in[1];
        di = (const int*)d_in[2];  ri = (const int*)d_in[3];
        rt = (const int*)d_in[4];  qr = (const int*)d_in[5];
        ob = (const int*)d_in[6];  oe = (const int*)d_in[7];
        rela = (const float*)d_in[8];  te = (const float*)d_in[9];
        Wp = (const float*)d_in[10]; Wn = (const float*)d_in[11];
        Wf = (const float*)d_in[12]; W1 = (const float*)d_in[13];
        W2 = (const float*)d_in[14]; Wc = (const float*)d_in[15];
        bc = (const float*)d_in[16];
    } else {
        rela = (const float*)d_in[0];  te = (const float*)d_in[1];
        Wp = (const float*)d_in[2]; Wn = (const float*)d_in[3];
        Wf = (const float*)d_in[4]; W1 = (const float*)d_in[5];
        W2 = (const float*)d_in[6]; Wc = (const float*)d_in[7];
        bc = (const float*)d_in[8];
        bt = (const int*)d_in[9];  si = (const int*)d_in[10];
        di = (const int*)d_in[11]; ri = (const int*)d_in[12];
        rt = (const int*)d_in[13]; qr = (const int*)d_in[14];
        ob = (const int*)d_in[15]; oe = (const int*)d_in[16];
    }

    float* out = (float*)d_out;

    cudaFuncSetAttribute(edge_kernel, cudaFuncAttributeMaxDynamicSharedMemorySize,
                         (3 * 4352 + 128 * 66) * 4);

    const int n4 = NN * NH / 4;
    zero_state_kernel<<<(n4 + 255) / 256, 256>>>();
    zero_out_kernel<<<(out_size + 255) / 256, 256>>>(out, out_size);

    part_reset_kernel<<<1, 32>>>();
    count_kernel<<<512, 256>>>(rt);
    offsets_kernel<<<1, 1>>>();
    scatter_kernel<<<512, 256>>>(rt, si, di, ri, bt);

    for (int layer = 0; layer < NL; ++layer) {
        const float* relaL = rela + layer * NRELP * NH;
        const float* W1L = W1 + layer * 5 * 192;
        rq_kernel<<<(NB * NRELP * 32 + 255) / 256, 256>>>(relaL, W1L, qr);
        if (layer > 0) hv_kernel<<<(NN * 32 + 255) / 256, 256>>>(W1L);
        edge_kernel<<<296, 256, (3 * 4352 + 128 * 66) * 4>>>(
            relaL, te, Wp, Wn, Wf, W2 + layer * 5, layer == 0 ? 1 : 0);
        relu_reset_kernel<<<(n4 + 255) / 256, 256>>>();
    }

    out_kernel<<<(NN * 32 + 255) / 256, 256>>>(Wc, bc, ob, oe, out);
}

// round 3
// speedup vs baseline: 4.6361x; 2.5550x over previous
#include <cuda_runtime.h>

#define NB 32
#define NN 100000
#define NE 1000000
#define NH 64
#define NL 3
#define NRELP 231
#define NTA 365
#define NENT 7128
#define FULLM 0xffffffffu
#define CH 1024
#define NCHUNK 98   // ceil(NN/CH)

typedef unsigned long long ull;

// ---------------- device scratch ----------------
static __device__ float g_hidden[NN * NH];        // 25.6 MB
static __device__ float g_next[NN * NH];          // 25.6 MB
static __device__ float g_hW[3 * NN * NH];        // 76.8 MB transformed hidden per class
static __device__ float g_RW[3 * NRELP * NH];     // rela @ W_cls^T
static __device__ float g_TW[3 * NTA * NH];       // time @ W_cls^T
static __device__ int4  g_eMeta[NE];              // sorted: {src|cls<<20, dst, rel|ta<<9, sci}
static __device__ float g_score[NE];
static __device__ float g_hv[NN * 8];
static __device__ float g_rq[NB * NRELP * 8];
static __device__ int   g_hist[NN];
static __device__ int   g_off[NN];
static __device__ int   g_part[NCHUNK];
static __device__ int   g_partoff[NCHUNK];

#define FMA2(d, a, b, c) \
    asm("fma.rn.f32x2 %0, %1, %2, %3;" : "=l"(d) : "l"(a), "l"(b), "l"(c))

__device__ __forceinline__ ull dup_f(float x) {
    ull r; unsigned u = __float_as_uint(x);
    asm("mov.b64 %0, {%1, %1};" : "=l"(r) : "r"(u));
    return r;
}
__device__ __forceinline__ void red2(float* p, float x, float y) {
    asm volatile("red.global.add.v2.f32 [%0], {%1, %2};" :: "l"(p), "f"(x), "f"(y) : "memory");
}

// ---------------- init ----------------
__global__ void zero_state_kernel() {
    int i = blockIdx.x * blockDim.x + threadIdx.x;
    const int n4 = NN * NH / 4;
    if (i < n4) {
        ((float4*)g_hidden)[i] = make_float4(0.f, 0.f, 0.f, 0.f);
        ((float4*)g_next)[i]   = make_float4(0.f, 0.f, 0.f, 0.f);
    }
}
__global__ void zero_out_kernel(float* out, int n) {
    int i = blockIdx.x * blockDim.x + threadIdx.x;
    if (i < n) out[i] = 0.f;
}

// ---------------- counting sort by src ----------------
__global__ void hist_zero_kernel() {
    int i = blockIdx.x * blockDim.x + threadIdx.x;
    if (i < NN) g_hist[i] = 0;
}
__global__ void hist_kernel(const int* __restrict__ src_idx) {
    int e = blockIdx.x * blockDim.x + threadIdx.x;
    if (e < NE) atomicAdd(&g_hist[src_idx[e]], 1);
}
__global__ void sum_chunk_kernel() {
    __shared__ int sd[256];
    int b = blockIdx.x, t = threadIdx.x;
    int s = 0;
    for (int i = t; i < CH; i += 256) {
        int g = b * CH + i;
        if (g < NN) s += g_hist[g];
    }
    sd[t] = s; __syncthreads();
    for (int o = 128; o; o >>= 1) { if (t < o) sd[t] += sd[t + o]; __syncthreads(); }
    if (t == 0) g_part[b] = sd[0];
}
__global__ void scan_part_kernel() {
    if (threadIdx.x == 0) {
        int run = 0;
        for (int i = 0; i < NCHUNK; ++i) { g_partoff[i] = run; run += g_part[i]; }
    }
}
__global__ void off_kernel() {
    __shared__ int sd[256];
    int b = blockIdx.x, t = threadIdx.x;
    int idx = b * CH + t * 4;
    int h0 = (idx + 0 < NN) ? g_hist[idx + 0] : 0;
    int h1 = (idx + 1 < NN) ? g_hist[idx + 1] : 0;
    int h2 = (idx + 2 < NN) ? g_hist[idx + 2] : 0;
    int h3 = (idx + 3 < NN) ? g_hist[idx + 3] : 0;
    int sum = h0 + h1 + h2 + h3;
    sd[t] = sum; __syncthreads();
    for (int o = 1; o < 256; o <<= 1) {
        int v = (t >= o) ? sd[t - o] : 0;
        __syncthreads();
        sd[t] += v;
        __syncthreads();
    }
    int base = g_partoff[b] + sd[t] - sum;
    if (idx + 0 < NN) g_off[idx + 0] = base;
    if (idx + 1 < NN) g_off[idx + 1] = base + h0;
    if (idx + 2 < NN) g_off[idx + 2] = base + h0 + h1;
    if (idx + 3 < NN) g_off[idx + 3] = base + h0 + h1 + h2;
}
__global__ void scatter_sort_kernel(const int* __restrict__ src_idx,
                                    const int* __restrict__ dst_idx,
                                    const int* __restrict__ rel_idx,
                                    const int* __restrict__ rel_time,
                                    const int* __restrict__ batch_idx) {
    int e = blockIdx.x * blockDim.x + threadIdx.x;
    if (e >= NE) return;
    int src = src_idx[e];
    int rt  = rel_time[e];
    int cls = rt > 0 ? 2 : (rt == 0 ? 1 : 0);  // 0=past(Wp) 1=now(Wn) 2=future(Wf)
    int ta  = rt < 0 ? -rt : rt;
    int rel = rel_idx[e];
    int pos = atomicAdd(&g_off[src], 1);
    g_eMeta[pos] = make_int4(src | (cls << 20), dst_idx[e],
                             rel | (ta << 9), batch_idx[e] * NRELP + rel);
}

// ---------------- per-layer precompute ----------------
// RW[cls][r][h] = sum_k rela[r][k] * W_cls[h][k];  TW[cls][ta][h] likewise for time.
__global__ void rwtw_kernel(const float* __restrict__ relaL,
                            const float* __restrict__ timeE,
                            const float* __restrict__ Wp,
                            const float* __restrict__ Wn,
                            const float* __restrict__ Wf) {
    int w = (blockIdx.x * blockDim.x + threadIdx.x) >> 5;
    int lane = threadIdx.x & 31;
    const int NROW = 3 * NRELP + 3 * NTA;   // 1788
    if (w >= NROW) return;
    const float* in; float* out; int cls;
    if (w < 3 * NRELP) {
        cls = w / NRELP;
        in = relaL + (w % NRELP) * NH;
        out = g_RW + w * NH;
    } else {
        int w2 = w - 3 * NRELP;
        cls = w2 / NTA;
        in = timeE + (w2 % NTA) * NH;
        out = g_TW + w2 * NH;
    }
    const float* W = (cls == 0) ? Wp : ((cls == 1) ? Wn : Wf);
    float2 ev = __ldg((const float2*)&in[2 * lane]);
    int h0 = 2 * lane;
    float a0 = 0.f, a1 = 0.f;
#pragma unroll 8
    for (int k2 = 0; k2 < 32; ++k2) {
        float bx = __shfl_sync(FULLM, ev.x, k2);
        float by = __shfl_sync(FULLM, ev.y, k2);
        float2 w0 = __ldg((const float2*)&W[h0 * 64 + 2 * k2]);
        float2 w1 = __ldg((const float2*)&W[(h0 + 1) * 64 + 2 * k2]);
        a0 += bx * w0.x + by * w0.y;
        a1 += bx * w1.x + by * w1.y;
    }
    out[h0] = a0; out[h0 + 1] = a1;
}

// hv[n][a] = hidden[n] . W1[l][a][0:64]
__global__ void hv_kernel(const float* __restrict__ W1L) {
    int w = (blockIdx.x * blockDim.x + threadIdx.x) >> 5;
    int lane = threadIdx.x & 31;
    if (w >= NN) return;
    float2 h = *(const float2*)&g_hidden[w * 64 + 2 * lane];
    float p[5];
#pragma unroll
    for (int a = 0; a < 5; ++a) {
        float2 u = __ldg((const float2*)&W1L[a * 192 + 2 * lane]);
        p[a] = h.x * u.x + h.y * u.y;
    }
#pragma unroll
    for (int a = 0; a < 5; ++a)
#pragma unroll
        for (int off = 16; off; off >>= 1) p[a] += __shfl_xor_sync(FULLM, p[a], off);
    if (lane == 0) {
#pragma unroll
        for (int a = 0; a < 5; ++a) g_hv[w * 8 + a] = p[a];
    }
}

// rq[b*231+r][a] = rela[r].W1seg1_a + rela[qr_b].W1seg2_a
__global__ void rq_kernel(const float* __restrict__ relaL,
                          const float* __restrict__ W1L,
                          const int* __restrict__ query_rel) {
    int w = (blockIdx.x * blockDim.x + threadIdx.x) >> 5;
    int lane = threadIdx.x & 31;
    if (w >= NB * NRELP) return;
    int b = w / NRELP, r = w % NRELP;
    int qrb = __ldg(&query_rel[b]);
    float2 re = __ldg((const float2*)&relaL[r * 64 + 2 * lane]);
    float2 qe = __ldg((const float2*)&relaL[qrb * 64 + 2 * lane]);
    float p[5];
#pragma unroll
    for (int a = 0; a < 5; ++a) {
        float2 v  = __ldg((const float2*)&W1L[a * 192 + 64 + 2 * lane]);
        float2 ww = __ldg((const float2*)&W1L[a * 192 + 128 + 2 * lane]);
        p[a] = re.x * v.x + re.y * v.y + qe.x * ww.x + qe.y * ww.y;
    }
#pragma unroll
    for (int a = 0; a < 5; ++a)
#pragma unroll
        for (int off = 16; off; off >>= 1) p[a] += __shfl_xor_sync(FULLM, p[a], off);
    if (lane == 0) {
#pragma unroll
        for (int a = 0; a < 5; ++a) g_rq[w * 8 + a] = p[a];
    }
}

// hW[cls][node] = hidden[node] @ W_cls^T   (3 dense GEMMs, tiled)
__global__ void __launch_bounds__(256) hw_kernel(const float* __restrict__ Wp,
                                                 const float* __restrict__ Wn,
                                                 const float* __restrict__ Wf) {
    extern __shared__ float dyn[];
    float* sW = dyn;            // 4352 floats
    float* sT = dyn + 4352;     // 128*66 floats
    int cls = blockIdx.y;
    const float* W = (cls == 0) ? Wp : ((cls == 1) ? Wn : Wf);
    int t = threadIdx.x;
    for (int idx = t; idx < 4096; idx += 256) {
        int h = idx >> 6, k = idx & 63;
        sW[k * 68 + h + (h >= 32 ? 4 : 0)] = __ldg(&W[h * 64 + k]);
    }
    __syncthreads();
    for (int tile = blockIdx.x * 128; tile < NN; tile += gridDim.x * 128) {
        int nN = min(128, NN - tile);
        for (int j = t; j < nN * 32; j += 256) {
            int nl = j >> 5, l = j & 31;
            *(float2*)&sT[nl * 66 + 2 * l] = *(const float2*)&g_hidden[(tile + nl) * 64 + 2 * l];
        }
        __syncthreads();
        int slot = t >> 1, p = t & 1;
        if (slot < nN) {
            const float* wb = sW + p * 36;
            const float* er = sT + slot * 66;
            ull acc[16];
#pragma unroll
            for (int j = 0; j < 16; ++j) acc[j] = 0ull;
#pragma unroll 4
            for (int k2 = 0; k2 < 32; ++k2) {
                float2 e2 = *(const float2*)&er[2 * k2];
                ull b0 = dup_f(e2.x);
                ull b1 = dup_f(e2.y);
                const float* r0 = wb + (2 * k2) * 68;
                const float* r1 = r0 + 68;
#pragma unroll
                for (int j = 0; j < 8; ++j) {
                    ulonglong2 w0 = *(const ulonglong2*)(r0 + 4 * j);
                    FMA2(acc[2 * j],     w0.x, b0, acc[2 * j]);
                    FMA2(acc[2 * j + 1], w0.y, b0, acc[2 * j + 1]);
                }
#pragma unroll
                for (int j = 0; j < 8; ++j) {
                    ulonglong2 w1 = *(const ulonglong2*)(r1 + 4 * j);
                    FMA2(acc[2 * j],     w1.x, b1, acc[2 * j]);
                    FMA2(acc[2 * j + 1], w1.y, b1, acc[2 * j + 1]);
                }
            }
            float* ob = g_hW + ((size_t)cls * NN + tile + slot) * 64 + p * 32;
#pragma unroll
            for (int j = 0; j < 8; ++j) {
                float2 lo = *(float2*)&acc[2 * j];
                float2 hi = *(float2*)&acc[2 * j + 1];
                *(float4*)(ob + 4 * j) = make_float4(lo.x, lo.y, hi.x, hi.y);
            }
        }
        __syncthreads();
    }
}

// ---------------- per-edge score ----------------
__global__ void score_kernel(const float* __restrict__ W2L, int isL0) {
    int e = blockIdx.x * blockDim.x + threadIdx.x;
    if (e >= NE) return;
    int4 m = __ldg(&g_eMeta[e]);
    int src = m.x & 0xFFFFF;
    const float4* rq4 = (const float4*)&g_rq[m.w * 8];
    float4 r0 = __ldg(&rq4[0]); float4 r1 = __ldg(&rq4[1]);
    float p0 = r0.x, p1 = r0.y, p2 = r0.z, p3 = r0.w, p4 = r1.x;
    if (!isL0) {
        const float4* hv4 = (const float4*)&g_hv[src * 8];
        float4 h0 = __ldg(&hv4[0]); float4 h1 = __ldg(&hv4[1]);
        p0 += h0.x; p1 += h0.y; p2 += h0.z; p3 += h0.w; p4 += h1.x;
    }
    float z = fmaxf(p0, 0.f) * __ldg(&W2L[0]) + fmaxf(p1, 0.f) * __ldg(&W2L[1])
            + fmaxf(p2, 0.f) * __ldg(&W2L[2]) + fmaxf(p3, 0.f) * __ldg(&W2L[3])
            + fmaxf(p4, 0.f) * __ldg(&W2L[4]);
    g_score[e] = 1.f / (1.f + __expf(-z));
}

// ---------------- main edge kernel: msg = score*(RW + TW + hW[src]); RED into dst ----------------
__global__ void __launch_bounds__(256) edge_kernel(int isL0) {
    int gw = (blockIdx.x * blockDim.x + threadIdx.x) >> 5;
    int lane = threadIdx.x & 31;
    int nw = (gridDim.x * blockDim.x) >> 5;
    for (int base = gw * 4; base < NE; base += nw * 4) {
#pragma unroll
        for (int t = 0; t < 4; ++t) {
            int e = base + t;
            int4 m = __ldg(&g_eMeta[e]);
            float s = __ldg(&g_score[e]);
            int src = m.x & 0xFFFFF;
            int cls = m.x >> 20;
            int rel = m.z & 511;
            int ta  = (m.z >> 9) & 511;
            float2 a = __ldg((const float2*)&g_RW[(cls * NRELP + rel) * 64 + 2 * lane]);
            float2 b = __ldg((const float2*)&g_TW[(cls * NTA + ta) * 64 + 2 * lane]);
            float vx = a.x + b.x, vy = a.y + b.y;
            if (!isL0) {
                float2 h = __ldg((const float2*)&g_hW[((size_t)cls * NN + src) * 64 + 2 * lane]);
                vx += h.x; vy += h.y;
            }
            red2(&g_next[m.y * 64 + 2 * lane], s * vx, s * vy);
        }
    }
}

// ---------------- hidden = relu(next); next = 0 ----------------
__global__ void relu_reset_kernel() {
    int i = blockIdx.x * blockDim.x + threadIdx.x;
    const int n4 = NN * NH / 4;
    if (i < n4) {
        float4 v = ((float4*)g_next)[i];
        v.x = fmaxf(v.x, 0.f); v.y = fmaxf(v.y, 0.f);
        v.z = fmaxf(v.z, 0.f); v.w = fmaxf(v.w, 0.f);
        ((float4*)g_hidden)[i] = v;
        ((float4*)g_next)[i] = make_float4(0.f, 0.f, 0.f, 0.f);
    }
}

// ---------------- output ----------------
__global__ void out_kernel(const float* __restrict__ Wc, const float* __restrict__ bc,
                           const int* __restrict__ ob, const int* __restrict__ oe,
                           float* __restrict__ out) {
    int gw = (blockIdx.x * blockDim.x + threadIdx.x) >> 5;
    int lane = threadIdx.x & 31;
    if (gw >= NN) return;
    float2 h = *(const float2*)&g_hidden[gw * 64 + 2 * lane];
    float2 w = __ldg((const float2*)&Wc[2 * lane]);
    float p = h.x * w.x + h.y * w.y;
#pragma unroll
    for (int off = 16; off; off >>= 1) p += __shfl_xor_sync(FULLM, p, off);
    if (lane == 0) out[ob[gw] * NENT + oe[gw]] = p + bc[0];
}

// ---------------- host launch ----------------
extern "C" void kernel_launch(void* const* d_in, const int* in_sizes, int n_in,
                              void* d_out, int out_size) {
    const int *bt, *si, *di, *ri, *rt, *qr, *ob, *oe;
    const float *rela, *te, *Wp, *Wn, *Wf, *W1, *W2, *Wc, *bc;

    if (in_sizes[0] == NE) {
        bt = (const int*)d_in[0];  si = (const int*)d_in[1];
        di = (const int*)d_in[2];  ri = (const int*)d_in[3];
        rt = (const int*)d_in[4];  qr = (const int*)d_in[5];
        ob = (const int*)d_in[6];  oe = (const int*)d_in[7];
        rela = (const float*)d_in[8];  te = (const float*)d_in[9];
        Wp = (const float*)d_in[10]; Wn = (const float*)d_in[11];
        Wf = (const float*)d_in[12]; W1 = (const float*)d_in[13];
        W2 = (const float*)d_in[14]; Wc = (const float*)d_in[15];
        bc = (const float*)d_in[16];
    } else {
        rela = (const float*)d_in[0];  te = (const float*)d_in[1];
        Wp = (const float*)d_in[2]; Wn = (const float*)d_in[3];
        Wf = (const float*)d_in[4]; W1 = (const float*)d_in[5];
        W2 = (const float*)d_in[6]; Wc = (const float*)d_in[7];
        bc = (const float*)d_in[8];
        bt = (const int*)d_in[9];  si = (const int*)d_in[10];
        di = (const int*)d_in[11]; ri = (const int*)d_in[12];
        rt = (const int*)d_in[13]; qr = (const int*)d_in[14];
        ob = (const int*)d_in[15]; oe = (const int*)d_in[16];
    }

    float* out = (float*)d_out;

    static int attr_done = 0;
    const int hw_smem = (4352 + 128 * 66) * 4;   // 51200 B
    if (!attr_done) {
        cudaFuncSetAttribute(hw_kernel, cudaFuncAttributeMaxDynamicSharedMemorySize, hw_smem);
        attr_done = 1;
    }

    const int n4 = NN * NH / 4;
    zero_state_kernel<<<(n4 + 255) / 256, 256>>>();
    zero_out_kernel<<<(out_size + 255) / 256, 256>>>(out, out_size);

    // counting sort by src
    hist_zero_kernel<<<(NN + 255) / 256, 256>>>();
    hist_kernel<<<(NE + 255) / 256, 256>>>(si);
    sum_chunk_kernel<<<NCHUNK, 256>>>();
    scan_part_kernel<<<1, 32>>>();
    off_kernel<<<NCHUNK, 256>>>();
    scatter_sort_kernel<<<(NE + 255) / 256, 256>>>(si, di, ri, rt, bt);

    for (int layer = 0; layer < NL; ++layer) {
        const float* relaL = rela + layer * NRELP * NH;
        const float* W1L = W1 + layer * 5 * 192;
        int isL0 = (layer == 0) ? 1 : 0;
        rwtw_kernel<<<(1788 * 32 + 255) / 256, 256>>>(relaL, te, Wp, Wn, Wf);
        rq_kernel<<<(NB * NRELP * 32 + 255) / 256, 256>>>(relaL, W1L, qr);
        if (!isL0) {
            hv_kernel<<<(NN * 32 + 255) / 256, 256>>>(W1L);
            hw_kernel<<<dim3((NN + 127) / 128, 3), 256, hw_smem>>>(Wp, Wn, Wf);
        }
        score_kernel<<<(NE + 255) / 256, 256>>>(W2 + layer * 5, isL0);
        edge_kernel<<<1184, 256>>>(isL0);
        relu_reset_kernel<<<(n4 + 255) / 256, 256>>>();
    }

    out_kernel<<<(NN * 32 + 255) / 256, 256>>>(Wc, bc, ob, oe, out);
}